// round 8
// baseline (speedup 1.0000x reference)
#include <cuda_runtime.h>

// Problem constants (fixed by the reference: x=(128,128,16,16) f32, logits=(128,100))
#define B_  128
#define D_  32768          // C*H*W
#define D4_ (D_/4)         // 8192 float4 per prototype row
#define K_  100
#define TI_ 5              // i-tile (streamed)
#define TJ_ 10             // j-tile (register-resident pj)
#define NTJ_ (K_ / TJ_)    // 10 j-tiles
#define NTI_ (K_ / TI_)    // 20 i-tiles

// Scratch (allocation-free rule: __device__ globals)
__device__ int   g_items[B_];    // CSR items: batch indices grouped by class, ascending
__device__ int   g_off[K_ + 1];  // CSR offsets
__device__ float g_inv[K_];      // 1/count (0 if count==0)

// ---------------------------------------------------------------------------
// Kernel 1: argmax per batch row + deterministic CSR build (single block).
// 1024 threads, 8 per row -> high MLP on the 51 KB logits read.
// softmax monotone -> argmax(probs) == argmax(logits); strict > + ascending
// scan + (value,index) shuffle reduce matches jnp.argmax tie-breaking.
// CSR: counts via smem atomics, serial smem prefix, stable rank scan ->
// bitwise-deterministic. PDL trigger at the end.
// ---------------------------------------------------------------------------
__global__ __launch_bounds__(1024) void argmax_csr_kernel(
        const float* __restrict__ logits) {
    __shared__ int s_cls[B_];
    __shared__ int s_cnt[K_];
    __shared__ int s_off[K_ + 1];

    int tid = threadIdx.x;        // 0..1023
    int b   = tid >> 3;           // row 0..127
    int sub = tid & 7;            // 0..7 within row

    if (tid < K_) s_cnt[tid] = 0;

    const float* row = logits + (size_t)b * K_;
    float v   = row[sub];
    int   idx = sub;
    #pragma unroll
    for (int k = sub + 8; k < K_; k += 8) {
        float t = row[k];
        if (t > v) { v = t; idx = k; }   // ascending + strict > => lowest index kept
    }
    #pragma unroll
    for (int off = 4; off > 0; off >>= 1) {
        float ov = __shfl_down_sync(0xffffffffu, v,   off, 8);
        int   oi = __shfl_down_sync(0xffffffffu, idx, off, 8);
        if (ov > v || (ov == v && oi < idx)) { v = ov; idx = oi; }
    }
    __syncthreads();              // counts zeroed before atomics
    if (sub == 0) {
        s_cls[b] = idx;
        atomicAdd(&s_cnt[idx], 1);
    }
    __syncthreads();

    if (tid == 0) {
        int off = 0;
        #pragma unroll 4
        for (int k = 0; k < K_; k++) { s_off[k] = off; off += s_cnt[k]; }
        s_off[K_] = off;
    }
    __syncthreads();

    if (tid < B_) {
        int myc = s_cls[tid];
        int rank = 0;
        #pragma unroll 8
        for (int bb = 0; bb < B_; bb++)
            rank += (bb < tid && s_cls[bb] == myc) ? 1 : 0;
        g_items[s_off[myc] + rank] = tid;
    }

    if (tid < K_) {
        g_off[tid] = s_off[tid];
        int c = s_cnt[tid];
        g_inv[tid] = (c > 0) ? (1.0f / (float)c) : 0.0f;
    }
    if (tid == 0) g_off[K_] = s_off[K_];

    cudaTriggerProgrammaticLaunchCompletion();
}

// ---------------------------------------------------------------------------
// Kernel 2 (fused): prototypes + inter-class matrix, 5x10 class tiles.
// grid = (D4/256, 200 tiles), block = 256.
// Finer tiles (6400 blocks at n_conc~592 -> 10.8 waves) shrink the wave-tail
// DRAM idle from ~22us to ~3.5us vs the old 10x10 / 5.4-wave layout.
// pj[10] recomputed from x in CSR order (bitwise-identical across blocks);
// pi (5 rows) streamed, reused from pj when the i-range lies inside the
// j-range. x (16 MB) and CSR are L2-resident. Proto output written by the
// blocks with i0 == j0 (exactly once per row). __stcs on all output: the
// 1.33 GB write stream is never re-read.
// ---------------------------------------------------------------------------
__global__ __launch_bounds__(256) void inter_fused_kernel(
        const float4* __restrict__ x4,
        float4* __restrict__ proto4,
        float4* __restrict__ out4) {
    __shared__ int   s_off[K_ + 1];
    __shared__ int   s_items[B_];
    __shared__ float s_inv[K_];

    // Wait for argmax_csr_kernel's g_* publishes (PDL dependency).
    cudaGridDependencySynchronize();

    int t = threadIdx.x;
    if (t < K_ + 1) s_off[t]   = g_off[t];
    if (t < B_)     s_items[t] = g_items[t];
    if (t < K_)     s_inv[t]   = g_inv[t];
    __syncthreads();

    const int d4     = blockIdx.x * 256 + t;       // 0..D4-1
    const int tile   = blockIdx.y;                 // 0..199
    const int tile_i = tile / NTJ_;                // 0..19
    const int tile_j = tile % NTJ_;                // 0..9
    const int i0 = tile_i * TI_;
    const int j0 = tile_j * TJ_;
    const bool i_in_j = (tile_i >> 1) == tile_j;   // i-range inside j-range
    const bool write_proto = (i0 == j0);           // tile_i == 2*tile_j

    // prototype rows j0..j0+9 (registers for the whole tile)
    float4 pj[TJ_];
    #pragma unroll
    for (int jj = 0; jj < TJ_; jj++) {
        const int k = j0 + jj;
        float4 acc = make_float4(0.f, 0.f, 0.f, 0.f);
        const int s = s_off[k], e = s_off[k + 1];
        for (int u = s; u < e; u++) {
            float4 v = x4[(size_t)s_items[u] * D4_ + d4];
            acc.x += v.x; acc.y += v.y; acc.z += v.z; acc.w += v.w;
        }
        const float inv = s_inv[k];  // count==0 -> acc==0, inv==0 -> 0 (matches where())
        acc.x *= inv; acc.y *= inv; acc.z *= inv; acc.w *= inv;
        pj[jj] = acc;
    }

    if (write_proto) {
        #pragma unroll
        for (int jj = 0; jj < TJ_; jj++)
            __stcs(&proto4[(size_t)(j0 + jj) * D4_ + d4], pj[jj]);
    }

    #pragma unroll
    for (int ii = 0; ii < TI_; ii++) {
        const int k = i0 + ii;
        float4 pi;
        if (i_in_j) {
            pi = pj[k - j0];
        } else {
            float4 acc = make_float4(0.f, 0.f, 0.f, 0.f);
            const int s = s_off[k], e = s_off[k + 1];
            for (int u = s; u < e; u++) {
                float4 v = x4[(size_t)s_items[u] * D4_ + d4];
                acc.x += v.x; acc.y += v.y; acc.z += v.z; acc.w += v.w;
            }
            const float inv = s_inv[k];
            acc.x *= inv; acc.y *= inv; acc.z *= inv; acc.w *= inv;
            pi = acc;
        }
        #pragma unroll
        for (int jj = 0; jj < TJ_; jj++) {
            float4 r;
            r.x = pj[jj].x - pi.x;
            r.y = pj[jj].y - pi.y;
            r.z = pj[jj].z - pi.z;
            r.w = pj[jj].w - pi.w;
            __stcs(&out4[(size_t)((k) * K_ + (j0 + jj)) * D4_ + d4], r);
        }
    }
}

// ---------------------------------------------------------------------------
// Launcher. Output layout: [prototypes (100*32768 f32) | inter (100*100*32768 f32)]
// ---------------------------------------------------------------------------
extern "C" void kernel_launch(void* const* d_in, const int* in_sizes, int n_in,
                              void* d_out, int out_size) {
    const float* x      = (const float*)d_in[0];   // (128,128,16,16) f32
    const float* logits = (const float*)d_in[1];   // (128,100) f32
    float* out = (float*)d_out;

    const float4* x4     = (const float4*)x;
    float4*       proto4 = (float4*)out;                       // first 819200 float4
    float4*       inter4 = (float4*)out + (size_t)K_ * D4_;    // rest

    argmax_csr_kernel<<<1, 1024>>>(logits);

    cudaLaunchConfig_t cfg = {};
    cfg.gridDim  = dim3(D4_ / 256, NTI_ * NTJ_);   // 32 x 200 tiles (5x10)
    cfg.blockDim = dim3(256);
    cfg.dynamicSmemBytes = 0;
    cfg.stream = 0;
    cudaLaunchAttribute attrs[1];
    attrs[0].id = cudaLaunchAttributeProgrammaticStreamSerialization;
    attrs[0].val.programmaticStreamSerializationAllowed = 1;
    cfg.attrs = attrs;
    cfg.numAttrs = 1;
    cudaLaunchKernelEx(&cfg, inter_fused_kernel, x4, proto4, inter4);
}

// round 9
// speedup vs baseline: 1.0800x; 1.0800x over previous
#include <cuda_runtime.h>

// Problem constants (fixed by the reference: x=(128,128,16,16) f32, logits=(128,100))
#define B_  128
#define D_  32768          // C*H*W
#define D4_ (D_/4)         // 8192 float4 per prototype row
#define K_  100
#define TILE_ 10           // 10x10 class tile
#define NCHUNK_ 32         // d4 chunks of 256
#define NTILES_ (NCHUNK_ * K_)   // 3200 logical tiles
#define NFULL_  2960             // tiles run as full blocks (5 waves x 592)
#define NBLOCKS_ (NFULL_ + 2 * (NTILES_ - NFULL_))   // 2960 + 480 = 3440

// Scratch (allocation-free rule: __device__ globals)
__device__ int   g_items[B_];    // CSR items: batch indices grouped by class, ascending
__device__ int   g_off[K_ + 1];  // CSR offsets
__device__ float g_inv[K_];      // 1/count (0 if count==0)

// ---------------------------------------------------------------------------
// Kernel 1: argmax per batch row + deterministic CSR build (single block).
// 1024 threads, 8 per row -> high MLP on the 51 KB logits read.
// softmax monotone -> argmax(probs) == argmax(logits); strict > + ascending
// scan + (value,index) shuffle reduce matches jnp.argmax tie-breaking.
// CSR: counts via smem atomics, serial smem prefix, stable rank scan ->
// bitwise-deterministic. PDL trigger at the end.
// ---------------------------------------------------------------------------
__global__ __launch_bounds__(1024) void argmax_csr_kernel(
        const float* __restrict__ logits) {
    __shared__ int s_cls[B_];
    __shared__ int s_cnt[K_];
    __shared__ int s_off[K_ + 1];

    int tid = threadIdx.x;        // 0..1023
    int b   = tid >> 3;           // row 0..127
    int sub = tid & 7;            // 0..7 within row

    if (tid < K_) s_cnt[tid] = 0;

    const float* row = logits + (size_t)b * K_;
    float v   = row[sub];
    int   idx = sub;
    #pragma unroll
    for (int k = sub + 8; k < K_; k += 8) {
        float t = row[k];
        if (t > v) { v = t; idx = k; }   // ascending + strict > => lowest index kept
    }
    #pragma unroll
    for (int off = 4; off > 0; off >>= 1) {
        float ov = __shfl_down_sync(0xffffffffu, v,   off, 8);
        int   oi = __shfl_down_sync(0xffffffffu, idx, off, 8);
        if (ov > v || (ov == v && oi < idx)) { v = ov; idx = oi; }
    }
    __syncthreads();              // counts zeroed before atomics
    if (sub == 0) {
        s_cls[b] = idx;
        atomicAdd(&s_cnt[idx], 1);
    }
    __syncthreads();

    if (tid == 0) {
        int off = 0;
        #pragma unroll 4
        for (int k = 0; k < K_; k++) { s_off[k] = off; off += s_cnt[k]; }
        s_off[K_] = off;
    }
    __syncthreads();

    if (tid < B_) {
        int myc = s_cls[tid];
        int rank = 0;
        #pragma unroll 8
        for (int bb = 0; bb < B_; bb++)
            rank += (bb < tid && s_cls[bb] == myc) ? 1 : 0;
        g_items[s_off[myc] + rank] = tid;
    }

    if (tid < K_) {
        g_off[tid] = s_off[tid];
        int c = s_cnt[tid];
        g_inv[tid] = (c > 0) ? (1.0f / (float)c) : 0.0f;
    }
    if (tid == 0) g_off[K_] = s_off[K_];

    cudaTriggerProgrammaticLaunchCompletion();
}

// ---------------------------------------------------------------------------
// Kernel 2 (fused): prototypes + inter-class matrix, mixed-granularity tiles.
// 3200 logical tiles = (d4 chunk 0..31) x (class tile 0..99, 10x10 classes).
// n_conc = 592 (148 SM x 4 blocks @ 64 regs). 3200/592 = 5.405 waves would
// quantize to 6 waves; instead the FIRST 2960 tiles (5 full waves) run as
// full blocks (identical to the previous best kernel), and the last 240
// tiles run as 480 half-blocks (i-range split 5+5, t/2 each), so the tail
// costs ~0.5 waves instead of 1.0 -> elapsed ~5.5t vs 6.0t.
// pj[10] recomputed from x in CSR order (bitwise-identical across blocks),
// pi streamed (register-reused on diagonal tiles). x (16 MB) + CSR are
// L2-resident. Proto output: diagonal tile, low half only -> once per row.
// __stcs on all output (1.33 GB write stream, never re-read).
// ---------------------------------------------------------------------------
__global__ __launch_bounds__(256) void inter_fused_kernel(
        const float4* __restrict__ x4,
        float4* __restrict__ proto4,
        float4* __restrict__ out4) {
    __shared__ int   s_off[K_ + 1];
    __shared__ int   s_items[B_];
    __shared__ float s_inv[K_];

    // Wait for argmax_csr_kernel's g_* publishes (PDL dependency).
    cudaGridDependencySynchronize();

    const int t = threadIdx.x;
    if (t < K_ + 1) s_off[t]   = g_off[t];
    if (t < B_)     s_items[t] = g_items[t];
    if (t < K_)     s_inv[t]   = g_inv[t];
    __syncthreads();

    // ---- block -> (tile, i-subrange) mapping ----
    const int bid = blockIdx.x;
    int tile_id, ilo, icnt;
    if (bid < NFULL_) {
        tile_id = bid;          ilo = 0;              icnt = TILE_;
    } else {
        const int h = bid - NFULL_;
        tile_id = NFULL_ + (h >> 1);
        ilo = (h & 1) * (TILE_ / 2);
        icnt = TILE_ / 2;
    }
    const int ct   = tile_id / NCHUNK_;            // class tile 0..99
    const int d4c  = tile_id % NCHUNK_;            // d4 chunk 0..31
    const int d4   = d4c * 256 + t;                // 0..D4-1
    const int i0   = (ct / TILE_) * TILE_;
    const int j0   = (ct % TILE_) * TILE_;
    const bool diag = (i0 == j0);

    // prototype rows j0..j0+9 (registers for the whole tile)
    float4 pj[TILE_];
    #pragma unroll
    for (int jj = 0; jj < TILE_; jj++) {
        const int k = j0 + jj;
        float4 acc = make_float4(0.f, 0.f, 0.f, 0.f);
        const int s = s_off[k], e = s_off[k + 1];
        for (int u = s; u < e; u++) {
            float4 v = x4[(size_t)s_items[u] * D4_ + d4];
            acc.x += v.x; acc.y += v.y; acc.z += v.z; acc.w += v.w;
        }
        const float inv = s_inv[k];  // count==0 -> acc==0, inv==0 -> 0 (matches where())
        acc.x *= inv; acc.y *= inv; acc.z *= inv; acc.w *= inv;
        pj[jj] = acc;
    }

    // proto output written exactly once per row: diagonal tile, low i-half
    if (diag && ilo == 0) {
        #pragma unroll
        for (int jj = 0; jj < TILE_; jj++)
            __stcs(&proto4[(size_t)(j0 + jj) * D4_ + d4], pj[jj]);
    }

    #pragma unroll
    for (int ii = 0; ii < TILE_; ii++) {
        if (ii >= icnt) break;
        const int k = i0 + ilo + ii;
        float4 pi;
        if (diag) {
            pi = pj[k - j0];
        } else {
            float4 acc = make_float4(0.f, 0.f, 0.f, 0.f);
            const int s = s_off[k], e = s_off[k + 1];
            for (int u = s; u < e; u++) {
                float4 v = x4[(size_t)s_items[u] * D4_ + d4];
                acc.x += v.x; acc.y += v.y; acc.z += v.z; acc.w += v.w;
            }
            const float inv = s_inv[k];
            acc.x *= inv; acc.y *= inv; acc.z *= inv; acc.w *= inv;
            pi = acc;
        }
        #pragma unroll
        for (int jj = 0; jj < TILE_; jj++) {
            float4 r;
            r.x = pj[jj].x - pi.x;
            r.y = pj[jj].y - pi.y;
            r.z = pj[jj].z - pi.z;
            r.w = pj[jj].w - pi.w;
            __stcs(&out4[(size_t)(k * K_ + (j0 + jj)) * D4_ + d4], r);
        }
    }
}

// ---------------------------------------------------------------------------
// Launcher. Output layout: [prototypes (100*32768 f32) | inter (100*100*32768 f32)]
// ---------------------------------------------------------------------------
extern "C" void kernel_launch(void* const* d_in, const int* in_sizes, int n_in,
                              void* d_out, int out_size) {
    const float* x      = (const float*)d_in[0];   // (128,128,16,16) f32
    const float* logits = (const float*)d_in[1];   // (128,100) f32
    float* out = (float*)d_out;

    const float4* x4     = (const float4*)x;
    float4*       proto4 = (float4*)out;                       // first 819200 float4
    float4*       inter4 = (float4*)out + (size_t)K_ * D4_;    // rest

    argmax_csr_kernel<<<1, 1024>>>(logits);

    cudaLaunchConfig_t cfg = {};
    cfg.gridDim  = dim3(NBLOCKS_);    // 3440 blocks: 2960 full + 480 half tiles
    cfg.blockDim = dim3(256);
    cfg.dynamicSmemBytes = 0;
    cfg.stream = 0;
    cudaLaunchAttribute attrs[1];
    attrs[0].id = cudaLaunchAttributeProgrammaticStreamSerialization;
    attrs[0].val.programmaticStreamSerializationAllowed = 1;
    cfg.attrs = attrs;
    cfg.numAttrs = 1;
    cudaLaunchKernelEx(&cfg, inter_fused_kernel, x4, proto4, inter4);
}